// round 13
// baseline (speedup 1.0000x reference)
#include <cuda_runtime.h>

// Problem shape (fixed by the reference)
#define BB 64
#define SS 2048
#define DD 256
#define NSPLIT 16
#define BATCH 8                      // in-flight float4 loads per thread
#define NBLK 4                       // 4 blocks of 32 contiguous rows per CTA
#define BROWS 32                     // rows per block (contiguous)

// Global scratch (statically zero-initialized; reset by the finalizing CTA each
// call so graph replays see a clean state).
__device__ float    g_sum [BB * DD];
__device__ unsigned g_maxo[BB * DD];   // order-preserving uint encoding
__device__ float    g_cnt [BB];
__device__ int      g_arrived[BB];

__device__ __forceinline__ float neg_inf() { return __int_as_float(0xff800000); }

__device__ __forceinline__ unsigned f2o(float f) {
    unsigned u = __float_as_uint(f);
    return (u & 0x80000000u) ? ~u : (u | 0x80000000u);
}
__device__ __forceinline__ float o2f(unsigned u) {
    return __uint_as_float((u & 0x80000000u) ? (u & 0x7fffffffu) : ~u);
}
__device__ __forceinline__ int arrive_acq_rel(int* addr) {
    int old;
    asm volatile("atom.add.acq_rel.gpu.global.s32 %0, [%1], 1;"
                 : "=r"(old) : "l"(addr) : "memory");
    return old;
}

// One CTA per (split, b). BLOCK-STRIDED assignment: CTA takes 4 CONTIGUOUS
// 32-row blocks at block indices {split, split+16, split+32, split+48}
// (rows 32*blk .. 32*blk+31). Within a block streaming is fully contiguous
// (DRAM page locality); across the 16 CTAs of a batch the valid work is
// balanced to +/- one block because block validity is a prefix in blk.
// Boundary blocks predicate each row's feats load on its warp-uniform mask
// (zero wasted traffic); after the prefix ends the CTA exits the scan early.
// 256 threads: d4 = tid % 64 (float4 lane over D=256), sg = tid / 64.
__global__ void __launch_bounds__(256, 4)
pool_blockstrided(const float* __restrict__ feats,
                  const float* __restrict__ mask,
                  float* __restrict__ out) {
    const int split = blockIdx.x;
    const int b     = blockIdx.y;
    const int tid   = threadIdx.x;
    const int d4    = tid & 63;
    const int sg    = tid >> 6;

    const float4* __restrict__ fbase =
        reinterpret_cast<const float4*>(feats) + (size_t)b * SS * 64;
    const float* __restrict__ mbase = mask + (size_t)b * SS;

    float4 sum = make_float4(0.f, 0.f, 0.f, 0.f);
    float4 mx  = make_float4(neg_inf(), neg_inf(), neg_inf(), neg_inf());
    float  cnt = 0.f;

    // Block k covers rows [32*(split + 16k), +32); thread handles rows
    // r0 + 4j + sg, j = 0..7 (contiguous, R8-style addressing within block).
    // Prime the mask pipeline with block 0.
    float mbuf[BATCH];
    {
        const int r0 = (split) * BROWS + sg;
#pragma unroll
        for (int j = 0; j < BATCH; ++j) mbuf[j] = __ldca(mbase + r0 + j * 4);
    }

    bool done = false;   // block validity is a prefix in blk (increasing s)
#pragma unroll
    for (int k = 0; k < NBLK; ++k) {
        if (done) break;

        bool allv = true, anyv = false;
#pragma unroll
        for (int j = 0; j < BATCH; ++j) {
            const bool v = (mbuf[j] > 0.f);
            allv &= v;
            anyv |= v;
        }

        // Prefetch next block's masks before touching feats
        float mnext[BATCH];
        if (k + 1 < NBLK) {
            const int rn = (split + 16 * (k + 1)) * BROWS + sg;
#pragma unroll
            for (int j = 0; j < BATCH; ++j) mnext[j] = __ldca(mbase + rn + j * 4);
        }

        const float4* __restrict__ pk =
            fbase + ((size_t)(split + 16 * k) * BROWS + sg) * 64 + d4;
        if (allv) {
            // Interior of the valid prefix: batched loads, select-free max.
            float4 fbuf[BATCH];
#pragma unroll
            for (int j = 0; j < BATCH; ++j) fbuf[j] = __ldcs(pk + j * 4 * 64);
#pragma unroll
            for (int j = 0; j < BATCH; ++j) {
                const float  m = mbuf[j];
                const float4 f = fbuf[j];
                cnt += m;
                sum.x += f.x * m;  sum.y += f.y * m;
                sum.z += f.z * m;  sum.w += f.w * m;
                mx.x = fmaxf(mx.x, f.x);
                mx.y = fmaxf(mx.y, f.y);
                mx.z = fmaxf(mx.z, f.z);
                mx.w = fmaxf(mx.w, f.w);
            }
        } else if (anyv) {
            // Boundary block: per-row predicated loads (warp-uniform mask) —
            // zero wasted traffic; valid rows need no select.
#pragma unroll
            for (int j = 0; j < BATCH; ++j) {
                const float m = mbuf[j];
                if (m > 0.f) {
                    const float4 f = __ldcs(pk + j * 4 * 64);
                    cnt += m;
                    sum.x += f.x * m;  sum.y += f.y * m;
                    sum.z += f.z * m;  sum.w += f.w * m;
                    mx.x = fmaxf(mx.x, f.x);
                    mx.y = fmaxf(mx.y, f.y);
                    mx.z = fmaxf(mx.z, f.z);
                    mx.w = fmaxf(mx.w, f.w);
                }
            }
            done = true;   // prefix ended inside this block
        } else {
            done = true;   // fully past the prefix
        }

#pragma unroll
        for (int j = 0; j < BATCH; ++j) mbuf[j] = mnext[j];
    }

    // CTA-level reduce: 4 sg-groups -> 1 (64 float4 lanes remain)
    __shared__ float4 s_sum[256];
    __shared__ float4 s_max[256];
    __shared__ float  s_cnt[4];
    s_sum[tid] = sum;
    s_max[tid] = mx;
    if (d4 == 0) s_cnt[sg] = cnt;
    __syncthreads();

    if (tid < 64) {
        const float ctot = s_cnt[0] + s_cnt[1] + s_cnt[2] + s_cnt[3];
        if (ctot > 0.f) {   // dead CTAs contribute identities — skip the flush
            float4 a = s_sum[tid];
            float4 m = s_max[tid];
#pragma unroll
            for (int k = 1; k < 4; ++k) {
                float4 a2 = s_sum[tid + 64 * k];
                float4 m2 = s_max[tid + 64 * k];
                a.x += a2.x; a.y += a2.y; a.z += a2.z; a.w += a2.w;
                m.x = fmaxf(m.x, m2.x); m.y = fmaxf(m.y, m2.y);
                m.z = fmaxf(m.z, m2.z); m.w = fmaxf(m.w, m2.w);
            }
            const int dbase = b * DD + tid * 4;
            atomicAdd(&g_sum[dbase + 0], a.x);
            atomicAdd(&g_sum[dbase + 1], a.y);
            atomicAdd(&g_sum[dbase + 2], a.z);
            atomicAdd(&g_sum[dbase + 3], a.w);
            atomicMax(&g_maxo[dbase + 0], f2o(m.x));
            atomicMax(&g_maxo[dbase + 1], f2o(m.y));
            atomicMax(&g_maxo[dbase + 2], f2o(m.z));
            atomicMax(&g_maxo[dbase + 3], f2o(m.w));
            if (tid == 0) atomicAdd(&g_cnt[b], ctot);
        }
    }

    // Arrival: syncthreads orders every thread's flushes before tid0's acq_rel add.
    __syncthreads();
    __shared__ int s_last;
    if (tid == 0)
        s_last = (arrive_acq_rel(&g_arrived[b]) == NSPLIT - 1);
    __syncthreads();
    if (!s_last) return;

    // Last CTA for this b: accumulators final (acquire above). Write output,
    // reset scratch for the next graph replay.
    {
        const int d = tid;  // 0..255
        float    fsum = __ldcg(&g_sum[b * DD + d]);
        unsigned mo   = __ldcg(&g_maxo[b * DD + d]);
        float    fcnt = __ldcg(&g_cnt[b]);
        out[(size_t)b * (2 * DD) + d]      = o2f(mo);
        out[(size_t)b * (2 * DD) + DD + d] = fsum / fcnt;
        __stcg(&g_sum[b * DD + d], 0.f);
        __stcg(&g_maxo[b * DD + d], 0u);
        if (tid == 0) {
            __stcg(&g_cnt[b], 0.f);
            __stcg(&g_arrived[b], 0);
        }
    }
}

extern "C" void kernel_launch(void* const* d_in, const int* in_sizes, int n_in,
                              void* d_out, int out_size) {
    const float* feats = (const float*)d_in[0];
    const float* mask  = (const float*)d_in[1];
    float* out = (float*)d_out;

    dim3 grid(NSPLIT, BB);
    pool_blockstrided<<<grid, 256>>>(feats, mask, out);
}